// round 13
// baseline (speedup 1.0000x reference)
#include <cuda_runtime.h>
#include <cuda_bf16.h>
#include <math.h>

#define CC 2048
#define GG 4
#define LL 512
#define NT 16384
#define EPSV 1e-4f
#define KS 16
#define KCH (NT/KS)
#define SQ_ITERS 12

typedef unsigned long long u64;
typedef unsigned int u32;
typedef unsigned short ush;

// ================= mma.sync / ldmatrix helpers =================
__device__ __forceinline__ u32 smem_u32(const void* p) {
    u32 a;
    asm("{ .reg .u64 t; cvta.to.shared.u64 t, %1; cvt.u32.u64 %0, t; }" : "=r"(a) : "l"(p));
    return a;
}
__device__ __forceinline__ void ldsm_x4(u32& r0, u32& r1, u32& r2, u32& r3, u32 addr) {
    asm volatile("ldmatrix.sync.aligned.m8n8.x4.shared.b16 {%0,%1,%2,%3}, [%4];"
                 : "=r"(r0), "=r"(r1), "=r"(r2), "=r"(r3) : "r"(addr));
}
__device__ __forceinline__ void ldsm_x2(u32& r0, u32& r1, u32 addr) {
    asm volatile("ldmatrix.sync.aligned.m8n8.x2.shared.b16 {%0,%1}, [%2];"
                 : "=r"(r0), "=r"(r1) : "r"(addr));
}
__device__ __forceinline__ void mma_bf16(float* c, u32 a0, u32 a1, u32 a2, u32 a3,
                                         u32 b0, u32 b1) {
    asm volatile(
        "mma.sync.aligned.m16n8k16.row.col.f32.bf16.bf16.f32 "
        "{%0,%1,%2,%3}, {%4,%5,%6,%7}, {%8,%9}, {%0,%1,%2,%3};"
        : "+f"(c[0]), "+f"(c[1]), "+f"(c[2]), "+f"(c[3])
        : "r"(a0), "r"(a1), "r"(a2), "r"(a3), "r"(b0), "r"(b1));
}
__device__ __forceinline__ u32 pack_bf16x2(float a, float b) {
    __nv_bfloat16 ha = __float2bfloat16(a), hb = __float2bfloat16(b);
    u32 r = ((u32)(*(ush*)&hb) << 16) | (u32)(*(ush*)&ha);
    return r;
}
__device__ __forceinline__ u32 pack_lo16x2(float a, float ha_f, float b, float hb_f) {
    __nv_bfloat16 la = __float2bfloat16(a - ha_f), lb = __float2bfloat16(b - hb_f);
    return ((u32)(*(ush*)&lb) << 16) | (u32)(*(ush*)&la);
}

// ================= device scratch =================
__device__ float g_part[KS][GG][LL][LL];
__device__ float g_A[GG][LL][LL];
__device__ float g_Y[2][GG][LL][LL];
__device__ float g_Z[2][GG][LL][LL];
__device__ float g_T[GG][LL][LL];
__device__ float g_M[2][GG][LL][LL];
__device__ float g_P[GG][LL][LL];
__device__ float g_mu[CC];
__device__ float g_pv[2][GG][LL];
__device__ float g_v[GG][LL];
__device__ float g_beta[CC];
__device__ float g_scal[16];
__device__ float g_red2[2][GG][16];
// bf16 split operands
__device__ __nv_bfloat16 gX_hi[(size_t)CC * NT];
__device__ __nv_bfloat16 gX_lo[(size_t)CC * NT];
__device__ __nv_bfloat16 gXT_hi[(size_t)GG * NT * LL];
__device__ __nv_bfloat16 gXT_lo[(size_t)GG * NT * LL];
__device__ __nv_bfloat16 gP_hi[GG][LL][LL];
__device__ __nv_bfloat16 gP_lo[GG][LL][LL];
// bf16 chain buffers: ids 0=Y0 1=Y1 2=Z0 3=Z1 4=T 5=M0 6=M1
__device__ __nv_bfloat16 g_bh[7][GG][LL][LL];
__device__ __nv_bfloat16 g_bl[7][GG][LL][LL];

__device__ __forceinline__ float* bufptr(int id) {
    switch (id) {
        case 0: return &g_Y[0][0][0][0];
        case 1: return &g_Y[1][0][0][0];
        case 2: return &g_Z[0][0][0][0];
        case 3: return &g_Z[1][0][0][0];
        case 4: return &g_T[0][0][0];
        case 5: return &g_M[0][0][0][0];
        default: return &g_M[1][0][0][0];
    }
}

// ================= mean =================
__global__ __launch_bounds__(256) void k_mean(const float* __restrict__ x) {
    __shared__ float sm[256];
    int c = blockIdx.x;
    const float4* row = (const float4*)(x + (size_t)c * NT);
    float s = 0.f;
    for (int i = threadIdx.x; i < NT / 4; i += 256) {
        float4 v = row[i];
        s += (v.x + v.y) + (v.z + v.w);
    }
    int t = threadIdx.x;
    sm[t] = s; __syncthreads();
    for (int o = 128; o > 0; o >>= 1) { if (t < o) sm[t] += sm[t + o]; __syncthreads(); }
    if (t == 0) g_mu[c] = sm[0] * (1.f / NT);
}

// ================= X -> bf16 hi/lo row-major AND transposed =================
__global__ __launch_bounds__(256) void k_cvt(const float* __restrict__ x) {
    __shared__ float ts[32][129];
    int g = blockIdx.z, k0 = blockIdx.y * 32, n0 = blockIdx.x * 128;
    int t = threadIdx.x;
    #pragma unroll
    for (int q = 0; q < 16; q++) {
        int idx = t + 256 * q;
        int r = idx >> 7, c = idx & 127;
        size_t o = (size_t)(g * LL + k0 + r) * NT + n0 + c;
        float v = x[o];
        ts[r][c] = v;
        __nv_bfloat16 h = __float2bfloat16(v);
        __nv_bfloat16 l = __float2bfloat16(v - __bfloat162float(h));
        gX_hi[o] = h;
        gX_lo[o] = l;
    }
    __syncthreads();
    #pragma unroll
    for (int q = 0; q < 2; q++) {
        int task = t + 256 * q;
        int n = task >> 2, oct = task & 3;
        union { ush s[8]; uint4 v; } ph, pl;
        #pragma unroll
        for (int e = 0; e < 8; e++) {
            float vv = ts[oct * 8 + e][n];
            __nv_bfloat16 h = __float2bfloat16(vv);
            float hf = __bfloat162float(h);
            __nv_bfloat16 l = __float2bfloat16(vv - hf);
            ph.s[e] = *(ush*)&h;
            pl.s[e] = *(ush*)&l;
        }
        size_t dst = (size_t)(g * NT + n0 + n) * LL + k0 + oct * 8;
        *(uint4*)&gXT_hi[dst] = ph.v;
        *(uint4*)&gXT_lo[dst] = pl.v;
    }
}

#define SRS 40   // smem row stride in bf16 elems (32 data + 8 pad)

// ================= cov partials via mma.sync bf16 split (round-12 proven) =================
__global__ __launch_bounds__(256) void k_cov_mma() {
    __shared__ __align__(16) ush sAh[128 * SRS];
    __shared__ __align__(16) ush sAl[128 * SRS];
    __shared__ __align__(16) ush sBh[128 * SRS];
    __shared__ __align__(16) ush sBl[128 * SRS];
    const int TIa[10] = {0,1,1,2,2,2,3,3,3,3};
    const int TJa[10] = {0,0,1,0,1,2,0,1,2,3};
    int t = threadIdx.x, lane = t & 31, wid = t >> 5;
    int wm = wid >> 2, wn = wid & 3;
    int ti = TIa[blockIdx.x] * 128, tj = TJa[blockIdx.x] * 128;
    int g = blockIdx.y, sp = blockIdx.z;

    const __nv_bfloat16* Ah = gX_hi + (size_t)(g * LL + ti) * NT + sp * KCH;
    const __nv_bfloat16* Al = gX_lo + (size_t)(g * LL + ti) * NT + sp * KCH;
    const __nv_bfloat16* Bh = gX_hi + (size_t)(g * LL + tj) * NT + sp * KCH;
    const __nv_bfloat16* Bl = gX_lo + (size_t)(g * LL + tj) * NT + sp * KCH;

    float acc[4][4][4];
    #pragma unroll
    for (int mi = 0; mi < 4; mi++)
        #pragma unroll
        for (int ni = 0; ni < 4; ni++)
            #pragma unroll
            for (int e = 0; e < 4; e++) acc[mi][ni][e] = 0.f;

    int aph = lane >> 3;
    int arow = (aph & 1) * 8 + (lane & 7);
    int acol = (aph >> 1) * 8;
    int brow = lane & 7;
    int bcol = ((lane >> 3) & 1) * 8;

    u32 bAh = smem_u32(sAh), bAl = smem_u32(sAl);
    u32 bBh = smem_u32(sBh), bBl = smem_u32(sBl);

    int ldr = t >> 2, ldc = (t & 3) * 8;

    for (int ck = 0; ck < KCH / 32; ck++) {
        int k0 = ck * 32;
        __syncthreads();
        #pragma unroll
        for (int q = 0; q < 2; q++) {
            int r = ldr + q * 64;
            u32 so = r * SRS + ldc;
            *(uint4*)&sAh[so] = *(const uint4*)(Ah + (size_t)r * NT + k0 + ldc);
            *(uint4*)&sAl[so] = *(const uint4*)(Al + (size_t)r * NT + k0 + ldc);
            *(uint4*)&sBh[so] = *(const uint4*)(Bh + (size_t)r * NT + k0 + ldc);
            *(uint4*)&sBl[so] = *(const uint4*)(Bl + (size_t)r * NT + k0 + ldc);
        }
        __syncthreads();
        #pragma unroll
        for (int kk = 0; kk < 32; kk += 16) {
            u32 Ahf[4][4], Alf[4][4];
            #pragma unroll
            for (int mi = 0; mi < 4; mi++) {
                u32 off = ((wm * 64 + mi * 16 + arow) * SRS + kk + acol) * 2;
                ldsm_x4(Ahf[mi][0], Ahf[mi][1], Ahf[mi][2], Ahf[mi][3], bAh + off);
                ldsm_x4(Alf[mi][0], Alf[mi][1], Alf[mi][2], Alf[mi][3], bAl + off);
            }
            #pragma unroll
            for (int ni = 0; ni < 4; ni++) {
                u32 off = ((wn * 32 + ni * 8 + brow) * SRS + kk + bcol) * 2;
                u32 bh0, bh1, bl0, bl1;
                ldsm_x2(bh0, bh1, bBh + off);
                ldsm_x2(bl0, bl1, bBl + off);
                #pragma unroll
                for (int mi = 0; mi < 4; mi++) {
                    mma_bf16(acc[mi][ni], Ahf[mi][0], Ahf[mi][1], Ahf[mi][2], Ahf[mi][3], bh0, bh1);
                    mma_bf16(acc[mi][ni], Ahf[mi][0], Ahf[mi][1], Ahf[mi][2], Ahf[mi][3], bl0, bl1);
                    mma_bf16(acc[mi][ni], Alf[mi][0], Alf[mi][1], Alf[mi][2], Alf[mi][3], bh0, bh1);
                }
            }
        }
    }

    float* base = &g_part[sp][g][0][0];
    #pragma unroll
    for (int mi = 0; mi < 4; mi++) {
        int r0 = ti + wm * 64 + mi * 16 + (lane >> 2);
        #pragma unroll
        for (int ni = 0; ni < 4; ni++) {
            int col = tj + wn * 32 + ni * 8 + 2 * (lane & 3);
            *(float2*)(base + (size_t)r0 * LL + col) =
                make_float2(acc[mi][ni][0], acc[mi][ni][1]);
            *(float2*)(base + (size_t)(r0 + 8) * LL + col) =
                make_float2(acc[mi][ni][2], acc[mi][ni][3]);
        }
    }
}

// ================= reduce partials -> A =================
__global__ __launch_bounds__(256) void k_cov_reduce() {
    int g = blockIdx.y;
    int idx = blockIdx.x * 256 + threadIdx.x;
    int i = idx >> 9, j = idx & 511;
    if (i < j) return;
    float s = 0.f;
    #pragma unroll
    for (int sp = 0; sp < KS; sp++) s += g_part[sp][g][i][j];
    float v = s * (1.f / NT) - g_mu[g * LL + i] * g_mu[g * LL + j];
    if (i == j) v += EPSV;
    g_A[g][i][j] = v;
    g_A[g][j][i] = v;
}

// ================= power iteration =================
__global__ void k_pi_init() {
    int idx = blockIdx.x * 256 + threadIdx.x;
    if (idx < GG * LL) {
        unsigned h = (unsigned)idx * 1103515245u + 12345u;
        ((float*)g_pv)[idx] = 0.5f + (float)(h & 1023u) * (1.0f / 1024.0f);
    }
}

__global__ __launch_bounds__(256) void k_matvec(int inb) {
    int g = blockIdx.y;
    __shared__ float vs[LL];
    for (int i = threadIdx.x; i < LL; i += 256) vs[i] = g_pv[inb][g][i];
    __syncthreads();
    int warp = threadIdx.x >> 5, lane = threadIdx.x & 31;
    int row0 = blockIdx.x * 32 + warp * 4;
    for (int r = 0; r < 4; r++) {
        int i = row0 + r;
        const float* Ar = &g_A[g][i][0];
        float s = 0.f;
        for (int k = lane; k < LL; k += 32) s += Ar[k] * vs[k];
        #pragma unroll
        for (int o = 16; o > 0; o >>= 1) s += __shfl_down_sync(0xffffffffu, s, o);
        if (lane == 0) g_pv[1 - inb][g][i] = s;
    }
}

__global__ void k_rq() {
    int g = blockIdx.x, i = threadIdx.x;
    __shared__ float r1[512], r2[512];
    float v = g_pv[0][g][i], u = g_pv[1][g][i];
    r1[i] = v * u; r2[i] = v * v; __syncthreads();
    for (int o = 256; o > 0; o >>= 1) {
        if (i < o) { r1[i] += r1[i + o]; r2[i] += r2[i + o]; }
        __syncthreads();
    }
    if (i == 0) g_scal[g] = r1[0] / r2[0];
}

// ================= NS init: Y0, T0 (bf16 hi/lo only) =================
__global__ __launch_bounds__(256) void k_ns_init() {
    int g = blockIdx.y;
    int idx = blockIdx.x * 256 + threadIdx.x;
    int i = idx >> 9, j = idx & 511;
    float invc = 1.0f / (1.05f * g_scal[g]);
    float y = g_A[g][i][j] * invc;
    float t0 = (i == j ? 1.5f : 0.0f) - 0.5f * y;
    __nv_bfloat16 yh = __float2bfloat16(y);
    g_bh[0][g][i][j] = yh;
    g_bl[0][g][i][j] = __float2bfloat16(y - __bfloat162float(yh));
    __nv_bfloat16 th = __float2bfloat16(t0);
    g_bh[2][g][i][j] = th;
    g_bl[2][g][i][j] = __float2bfloat16(t0 - __bfloat162float(th));
}

// ================= M0 = sigma I - A (bf16) + fnorm partials =================
__global__ __launch_bounds__(256) void k_shift() {
    int g = blockIdx.y;
    int base = blockIdx.x * 16384;
    float sigma = 1.15f * g_scal[g];
    float ss = 0.f;
    for (int q = 0; q < 64; q++) {
        int idx = base + threadIdx.x + 256 * q;
        int i = idx >> 9, j = idx & 511;
        float v = (i == j ? sigma : 0.0f) - g_A[g][i][j];
        __nv_bfloat16 h = __float2bfloat16(v);
        g_bh[5][g][i][j] = h;
        g_bl[5][g][i][j] = __float2bfloat16(v - __bfloat162float(h));
        ss += v * v;
    }
    __shared__ float rsm[256];
    int t = threadIdx.x;
    rsm[t] = ss; __syncthreads();
    for (int o = 128; o > 0; o >>= 1) { if (t < o) rsm[t] += rsm[t + o]; __syncthreads(); }
    if (t == 0) g_red2[0][g][blockIdx.x] = rsm[0];
}

// ================= chain GEMM via mma.sync bf16 split =================
// All chain matrices are symmetric (polynomials in A), so the col-major B
// fragment is fed from ROWS of B — identical structure to k_cov_mma.
// mode 0: C = 1.5 I - 0.5 (A B) ; mode 1: C = A B ;
// mode 2: C = (A B) * rsqrt(sum g_red2[rs]); block sumsq -> g_red2[ws]
// Epilogue writes fp32 C and bf16 hi/lo C.
__global__ __launch_bounds__(256) void k_chain_mma(int ida, int idb, int idc,
                                                   int mode, int rs, int ws) {
    __shared__ __align__(16) ush sAh[128 * SRS];
    __shared__ __align__(16) ush sAl[128 * SRS];
    __shared__ __align__(16) ush sBh[128 * SRS];
    __shared__ __align__(16) ush sBl[128 * SRS];
    int t = threadIdx.x, lane = t & 31, wid = t >> 5;
    int wm = wid >> 2, wn = wid & 3;
    int i0 = blockIdx.y * 128, j0 = blockIdx.x * 128;
    int g = blockIdx.z;

    const __nv_bfloat16* Ah = &g_bh[ida][g][i0][0];
    const __nv_bfloat16* Al = &g_bl[ida][g][i0][0];
    const __nv_bfloat16* Bh = &g_bh[idb][g][j0][0];
    const __nv_bfloat16* Bl = &g_bl[idb][g][j0][0];

    float scale = 1.0f;
    if (mode == 2) {
        float fs = 0.f;
        #pragma unroll
        for (int q = 0; q < 16; q++) fs += g_red2[rs][g][q];
        scale = rsqrtf(fs);
    }

    float acc[4][4][4];
    #pragma unroll
    for (int mi = 0; mi < 4; mi++)
        #pragma unroll
        for (int ni = 0; ni < 4; ni++)
            #pragma unroll
            for (int e = 0; e < 4; e++) acc[mi][ni][e] = 0.f;

    int aph = lane >> 3;
    int arow = (aph & 1) * 8 + (lane & 7);
    int acol = (aph >> 1) * 8;
    int brow = lane & 7;
    int bcol = ((lane >> 3) & 1) * 8;

    u32 bAh = smem_u32(sAh), bAl = smem_u32(sAl);
    u32 bBh = smem_u32(sBh), bBl = smem_u32(sBl);

    int ldr = t >> 2, ldc = (t & 3) * 8;

    for (int ck = 0; ck < 16; ck++) {
        int k0 = ck * 32;
        __syncthreads();
        #pragma unroll
        for (int q = 0; q < 2; q++) {
            int r = ldr + q * 64;
            u32 so = r * SRS + ldc;
            *(uint4*)&sAh[so] = *(const uint4*)(Ah + (size_t)r * LL + k0 + ldc);
            *(uint4*)&sAl[so] = *(const uint4*)(Al + (size_t)r * LL + k0 + ldc);
            *(uint4*)&sBh[so] = *(const uint4*)(Bh + (size_t)r * LL + k0 + ldc);
            *(uint4*)&sBl[so] = *(const uint4*)(Bl + (size_t)r * LL + k0 + ldc);
        }
        __syncthreads();
        #pragma unroll
        for (int kk = 0; kk < 32; kk += 16) {
            u32 Ahf[4][4], Alf[4][4];
            #pragma unroll
            for (int mi = 0; mi < 4; mi++) {
                u32 off = ((wm * 64 + mi * 16 + arow) * SRS + kk + acol) * 2;
                ldsm_x4(Ahf[mi][0], Ahf[mi][1], Ahf[mi][2], Ahf[mi][3], bAh + off);
                ldsm_x4(Alf[mi][0], Alf[mi][1], Alf[mi][2], Alf[mi][3], bAl + off);
            }
            #pragma unroll
            for (int ni = 0; ni < 4; ni++) {
                u32 off = ((wn * 32 + ni * 8 + brow) * SRS + kk + bcol) * 2;
                u32 bh0, bh1, bl0, bl1;
                ldsm_x2(bh0, bh1, bBh + off);
                ldsm_x2(bl0, bl1, bBl + off);
                #pragma unroll
                for (int mi = 0; mi < 4; mi++) {
                    mma_bf16(acc[mi][ni], Ahf[mi][0], Ahf[mi][1], Ahf[mi][2], Ahf[mi][3], bh0, bh1);
                    mma_bf16(acc[mi][ni], Ahf[mi][0], Ahf[mi][1], Ahf[mi][2], Ahf[mi][3], bl0, bl1);
                    mma_bf16(acc[mi][ni], Alf[mi][0], Alf[mi][1], Alf[mi][2], Alf[mi][3], bh0, bh1);
                }
            }
        }
    }

    // epilogue: transform, write fp32 C + bf16 hi/lo C; mode-2 sumsq
    float* Cf = bufptr(idc) + (size_t)g * LL * LL;
    __nv_bfloat16* Ch = &g_bh[idc][g][0][0];
    __nv_bfloat16* Cl = &g_bl[idc][g][0][0];
    float ss = 0.f;
    #pragma unroll
    for (int mi = 0; mi < 4; mi++) {
        int r0 = i0 + wm * 64 + mi * 16 + (lane >> 2);
        int r1 = r0 + 8;
        #pragma unroll
        for (int ni = 0; ni < 4; ni++) {
            int col = j0 + wn * 32 + ni * 8 + 2 * (lane & 3);
            float v00 = acc[mi][ni][0], v01 = acc[mi][ni][1];
            float v10 = acc[mi][ni][2], v11 = acc[mi][ni][3];
            if (mode == 0) {
                v00 = (r0 == col     ? 1.5f : 0.0f) - 0.5f * v00;
                v01 = (r0 == col + 1 ? 1.5f : 0.0f) - 0.5f * v01;
                v10 = (r1 == col     ? 1.5f : 0.0f) - 0.5f * v10;
                v11 = (r1 == col + 1 ? 1.5f : 0.0f) - 0.5f * v11;
            } else if (mode == 2) {
                v00 *= scale; v01 *= scale; v10 *= scale; v11 *= scale;
                ss += v00 * v00 + v01 * v01 + v10 * v10 + v11 * v11;
            }
            *(float2*)(Cf + (size_t)r0 * LL + col) = make_float2(v00, v01);
            *(float2*)(Cf + (size_t)r1 * LL + col) = make_float2(v10, v11);
            // bf16 split
            __nv_bfloat16 h00 = __float2bfloat16(v00), h01 = __float2bfloat16(v01);
            __nv_bfloat16 h10 = __float2bfloat16(v10), h11 = __float2bfloat16(v11);
            u32 hp0 = ((u32)(*(ush*)&h01) << 16) | (u32)(*(ush*)&h00);
            u32 hp1 = ((u32)(*(ush*)&h11) << 16) | (u32)(*(ush*)&h10);
            *(u32*)(Ch + (size_t)r0 * LL + col) = hp0;
            *(u32*)(Ch + (size_t)r1 * LL + col) = hp1;
            __nv_bfloat16 l00 = __float2bfloat16(v00 - __bfloat162float(h00));
            __nv_bfloat16 l01 = __float2bfloat16(v01 - __bfloat162float(h01));
            __nv_bfloat16 l10 = __float2bfloat16(v10 - __bfloat162float(h10));
            __nv_bfloat16 l11 = __float2bfloat16(v11 - __bfloat162float(h11));
            u32 lp0 = ((u32)(*(ush*)&l01) << 16) | (u32)(*(ush*)&l00);
            u32 lp1 = ((u32)(*(ush*)&l11) << 16) | (u32)(*(ush*)&l10);
            *(u32*)(Cl + (size_t)r0 * LL + col) = lp0;
            *(u32*)(Cl + (size_t)r1 * LL + col) = lp1;
        }
    }
    if (mode == 2) {
        __shared__ float rsm[256];
        rsm[t] = ss; __syncthreads();
        for (int o = 128; o > 0; o >>= 1) { if (t < o) rsm[t] += rsm[t + o]; __syncthreads(); }
        if (t == 0) g_red2[ws][g][blockIdx.y * 4 + blockIdx.x] = rsm[0];
    }
}

// ================= eigenvector extraction =================
__global__ void k_colnorm() {
    int g = blockIdx.x, j = threadIdx.x;
    const float* M = &g_M[0][g][0][0];
    float s = 0.f;
    for (int i = 0; i < LL; i++) { float m = M[(size_t)i * LL + j]; s += m * m; }
    __shared__ float sv[512]; __shared__ int si[512];
    sv[j] = s; si[j] = j; __syncthreads();
    for (int o = 256; o > 0; o >>= 1) {
        if (j < o) { if (sv[j + o] > sv[j]) { sv[j] = sv[j + o]; si[j] = si[j + o]; } }
        __syncthreads();
    }
    int jm = si[0];
    float inv = rsqrtf(sv[0]);
    g_v[g][j] = M[(size_t)j * LL + jm] * inv;
}

__global__ void k_rayleigh() {
    int g = blockIdx.x, i = threadIdx.x;
    __shared__ float vs[512];
    vs[i] = g_v[g][i]; __syncthreads();
    float u = 0.f;
    const float* Ac = &g_A[g][0][0];
    for (int k = 0; k < 512; k++) u = fmaf(Ac[(size_t)k * 512 + i], vs[k], u);
    __shared__ float r1[512], r2[512];
    r1[i] = u * vs[i]; r2[i] = vs[i] * vs[i]; __syncthreads();
    for (int o = 256; o > 0; o >>= 1) {
        if (i < o) { r1[i] += r1[i + o]; r2[i] += r2[i + o]; }
        __syncthreads();
    }
    if (i == 0) g_scal[8 + g] = r1[0] / r2[0];
}

// ================= P = Z/sqrt(c) - lam^{-1/2} v v^T (+ bf16 split) =================
__global__ __launch_bounds__(256) void k_subspace(int zid) {
    int g = blockIdx.y;
    int idx = blockIdx.x * 256 + threadIdx.x;
    int i = idx >> 9, j = idx & 511;
    const float* Z = bufptr(zid) + (size_t)g * LL * LL;
    float c = 1.05f * g_scal[g];
    float lam = g_scal[8 + g];
    float p = Z[(size_t)i * 512 + j] * rsqrtf(c) - rsqrtf(lam) * g_v[g][i] * g_v[g][j];
    g_P[g][i][j] = p;
    __nv_bfloat16 h = __float2bfloat16(p);
    gP_hi[g][i][j] = h;
    gP_lo[g][i][j] = __float2bfloat16(p - __bfloat162float(h));
}

// ================= beta = bias - w * (P mu) =================
__global__ void k_beta(const float* __restrict__ w, const float* __restrict__ b) {
    int g = blockIdx.x, i = threadIdx.x;
    __shared__ float mus[512];
    mus[i] = g_mu[g * LL + i]; __syncthreads();
    float s = 0.f;
    const float* Pc = &g_P[g][0][0];
    for (int k = 0; k < 512; k++) s = fmaf(Pc[(size_t)k * 512 + i], mus[k], s);
    int c = g * LL + i;
    g_beta[c] = b[c] - w[c] * s;
}

// ================= apply via mma.sync bf16 split (round-11 proven) =================
__global__ __launch_bounds__(256) void k_apply_mma(const float* __restrict__ w,
                                                   float* __restrict__ out) {
    __shared__ __align__(16) ush sAh[128 * SRS];
    __shared__ __align__(16) ush sAl[128 * SRS];
    __shared__ __align__(16) ush sBh[128 * SRS];
    __shared__ __align__(16) ush sBl[128 * SRS];
    int t = threadIdx.x, lane = t & 31, wid = t >> 5;
    int wm = wid >> 2, wn = wid & 3;
    int n0 = blockIdx.x * 128, i0 = blockIdx.y * 128, g = blockIdx.z;

    const __nv_bfloat16* Ph = &gP_hi[g][0][0];
    const __nv_bfloat16* Pl = &gP_lo[g][0][0];
    const __nv_bfloat16* Xh = gXT_hi + (size_t)g * NT * LL;
    const __nv_bfloat16* Xl = gXT_lo + (size_t)g * NT * LL;

    float acc[4][4][4];
    #pragma unroll
    for (int mi = 0; mi < 4; mi++)
        #pragma unroll
        for (int ni = 0; ni < 4; ni++)
            #pragma unroll
            for (int e = 0; e < 4; e++) acc[mi][ni][e] = 0.f;

    int aph = lane >> 3;
    int arow = (aph & 1) * 8 + (lane & 7);
    int acol = (aph >> 1) * 8;
    int brow = lane & 7;
    int bcol = ((lane >> 3) & 1) * 8;

    u32 bAh = smem_u32(sAh), bAl = smem_u32(sAl);
    u32 bBh = smem_u32(sBh), bBl = smem_u32(sBl);

    int ldr = t >> 2, ldc = (t & 3) * 8;

    for (int ck = 0; ck < 16; ck++) {
        int k0 = ck * 32;
        __syncthreads();
        #pragma unroll
        for (int q = 0; q < 2; q++) {
            int r = ldr + q * 64;
            u32 so = r * SRS + ldc;
            *(uint4*)&sAh[so] = *(const uint4*)(Ph + (size_t)(i0 + r) * LL + k0 + ldc);
            *(uint4*)&sAl[so] = *(const uint4*)(Pl + (size_t)(i0 + r) * LL + k0 + ldc);
            *(uint4*)&sBh[so] = *(const uint4*)(Xh + (size_t)(n0 + r) * LL + k0 + ldc);
            *(uint4*)&sBl[so] = *(const uint4*)(Xl + (size_t)(n0 + r) * LL + k0 + ldc);
        }
        __syncthreads();
        #pragma unroll
        for (int kk = 0; kk < 32; kk += 16) {
            u32 Ahf[4][4], Alf[4][4];
            #pragma unroll
            for (int mi = 0; mi < 4; mi++) {
                u32 off = ((wm * 64 + mi * 16 + arow) * SRS + kk + acol) * 2;
                ldsm_x4(Ahf[mi][0], Ahf[mi][1], Ahf[mi][2], Ahf[mi][3], bAh + off);
                ldsm_x4(Alf[mi][0], Alf[mi][1], Alf[mi][2], Alf[mi][3], bAl + off);
            }
            #pragma unroll
            for (int ni = 0; ni < 4; ni++) {
                u32 off = ((wn * 32 + ni * 8 + brow) * SRS + kk + bcol) * 2;
                u32 bh0, bh1, bl0, bl1;
                ldsm_x2(bh0, bh1, bBh + off);
                ldsm_x2(bl0, bl1, bBl + off);
                #pragma unroll
                for (int mi = 0; mi < 4; mi++) {
                    mma_bf16(acc[mi][ni], Ahf[mi][0], Ahf[mi][1], Ahf[mi][2], Ahf[mi][3], bh0, bh1);
                    mma_bf16(acc[mi][ni], Ahf[mi][0], Ahf[mi][1], Ahf[mi][2], Ahf[mi][3], bl0, bl1);
                    mma_bf16(acc[mi][ni], Alf[mi][0], Alf[mi][1], Alf[mi][2], Alf[mi][3], bh0, bh1);
                }
            }
        }
    }

    #pragma unroll
    for (int mi = 0; mi < 4; mi++) {
        int r0 = i0 + wm * 64 + mi * 16 + (lane >> 2);
        int ch0 = g * LL + r0, ch1 = ch0 + 8;
        float w0 = w[ch0], be0 = g_beta[ch0];
        float w1 = w[ch1], be1 = g_beta[ch1];
        #pragma unroll
        for (int ni = 0; ni < 4; ni++) {
            int col = n0 + wn * 32 + ni * 8 + 2 * (lane & 3);
            float2 v0, v1;
            v0.x = fmaf(w0, acc[mi][ni][0], be0);
            v0.y = fmaf(w0, acc[mi][ni][1], be0);
            v1.x = fmaf(w1, acc[mi][ni][2], be1);
            v1.y = fmaf(w1, acc[mi][ni][3], be1);
            *(float2*)(out + (size_t)ch0 * NT + col) = v0;
            *(float2*)(out + (size_t)ch1 * NT + col) = v1;
        }
    }
}

// ================= launch =================
extern "C" void kernel_launch(void* const* d_in, const int* in_sizes, int n_in,
                              void* d_out, int out_size) {
    const float* x = (const float*)d_in[0];
    const float* w = (const float*)d_in[1];
    const float* b = (const float*)d_in[2];
    float* out = (float*)d_out;

    k_mean<<<CC, 256>>>(x);
    k_cvt<<<dim3(128, 16, GG), 256>>>(x);
    k_cov_mma<<<dim3(10, GG, KS), 256>>>();
    k_cov_reduce<<<dim3(1024, GG), 256>>>();

    k_pi_init<<<8, 256>>>();
    for (int m = 0; m < 7; m++)
        k_matvec<<<dim3(16, GG), 256>>>(m & 1);
    k_rq<<<GG, 512>>>();

    k_ns_init<<<dim3(1024, GG), 256>>>();
    dim3 cg(4, 4, GG);
    k_chain_mma<<<cg, 256>>>(0, 2, 1, 1, 0, 0);   // Y1 = Y0 T0
    k_chain_mma<<<cg, 256>>>(2, 1, 4, 0, 0, 0);   // T  = 1.5I - 0.5 Z1 Y1
    k_chain_mma<<<cg, 256>>>(1, 4, 0, 1, 0, 0);   // Y2
    k_chain_mma<<<cg, 256>>>(4, 2, 3, 1, 0, 0);   // Z2
    k_chain_mma<<<cg, 256>>>(3, 0, 4, 0, 0, 0);   // T
    k_chain_mma<<<cg, 256>>>(0, 4, 1, 1, 0, 0);   // Y3
    k_chain_mma<<<cg, 256>>>(4, 3, 2, 1, 0, 0);   // Z3
    k_chain_mma<<<cg, 256>>>(2, 1, 4, 0, 0, 0);   // T
    k_chain_mma<<<cg, 256>>>(4, 2, 3, 1, 0, 0);   // Z4 -> buf 3 (final, fp32 too)

    k_shift<<<dim3(16, GG), 256>>>();
    for (int k = 0; k < SQ_ITERS; k++) {
        int inb = 5 + (k & 1), outb = 5 + 1 - (k & 1);
        k_chain_mma<<<cg, 256>>>(inb, inb, outb, 2, k & 1, 1 - (k & 1));
    }

    k_colnorm<<<GG, 512>>>();
    k_rayleigh<<<GG, 512>>>();
    k_subspace<<<dim3(1024, GG), 256>>>(3);
    k_beta<<<GG, 512>>>(w, b);
    k_apply_mma<<<dim3(128, 4, GG), 256>>>(w, out);
}

// round 14
// speedup vs baseline: 1.1740x; 1.1740x over previous
#include <cuda_runtime.h>
#include <cuda_bf16.h>
#include <math.h>

#define CC 2048
#define GG 4
#define LL 512
#define NT 16384
#define EPSV 1e-4f
#define KS 4
#define KCH (NT/KS)
#define SQ_ITERS 10

typedef unsigned long long u64;
typedef unsigned int u32;
typedef unsigned short ush;

// ================= mma.sync / ldmatrix helpers =================
__device__ __forceinline__ u32 smem_u32(const void* p) {
    u32 a;
    asm("{ .reg .u64 t; cvta.to.shared.u64 t, %1; cvt.u32.u64 %0, t; }" : "=r"(a) : "l"(p));
    return a;
}
__device__ __forceinline__ void ldsm_x4(u32& r0, u32& r1, u32& r2, u32& r3, u32 addr) {
    asm volatile("ldmatrix.sync.aligned.m8n8.x4.shared.b16 {%0,%1,%2,%3}, [%4];"
                 : "=r"(r0), "=r"(r1), "=r"(r2), "=r"(r3) : "r"(addr));
}
__device__ __forceinline__ void ldsm_x2(u32& r0, u32& r1, u32 addr) {
    asm volatile("ldmatrix.sync.aligned.m8n8.x2.shared.b16 {%0,%1}, [%2];"
                 : "=r"(r0), "=r"(r1) : "r"(addr));
}
__device__ __forceinline__ void mma_bf16(float* c, u32 a0, u32 a1, u32 a2, u32 a3,
                                         u32 b0, u32 b1) {
    asm volatile(
        "mma.sync.aligned.m16n8k16.row.col.f32.bf16.bf16.f32 "
        "{%0,%1,%2,%3}, {%4,%5,%6,%7}, {%8,%9}, {%0,%1,%2,%3};"
        : "+f"(c[0]), "+f"(c[1]), "+f"(c[2]), "+f"(c[3])
        : "r"(a0), "r"(a1), "r"(a2), "r"(a3), "r"(b0), "r"(b1));
}

struct ChainOp { int ida, idb, idc, mode, rs, ws, wf; };

// ================= device scratch =================
__device__ float g_part[KS][GG][LL][LL];
__device__ float g_A[GG][LL][LL];
__device__ float g_Y[2][GG][LL][LL];
__device__ float g_Z[2][GG][LL][LL];
__device__ float g_T[GG][LL][LL];
__device__ float g_M[2][GG][LL][LL];
__device__ float g_P[GG][LL][LL];
__device__ float g_mu[CC];
__device__ float g_pv[2][GG][LL];
__device__ float g_v[GG][LL];
__device__ float g_beta[CC];
__device__ float g_scal[16];
__device__ float g_red2[2][GG][16];
// bf16 split operands
__device__ __nv_bfloat16 gX_hi[(size_t)CC * NT];
__device__ __nv_bfloat16 gX_lo[(size_t)CC * NT];
__device__ __nv_bfloat16 gXT_hi[(size_t)GG * NT * LL];
__device__ __nv_bfloat16 gXT_lo[(size_t)GG * NT * LL];
__device__ __nv_bfloat16 gP_hi[GG][LL][LL];
__device__ __nv_bfloat16 gP_lo[GG][LL][LL];
// bf16 chain buffers: ids 0=Y0 1=Y1 2=Z0 3=Z1 4=T 5=M0 6=M1
__device__ __nv_bfloat16 g_bh[7][GG][LL][LL];
__device__ __nv_bfloat16 g_bl[7][GG][LL][LL];

__device__ __forceinline__ float* bufptr(int id) {
    switch (id) {
        case 0: return &g_Y[0][0][0][0];
        case 1: return &g_Y[1][0][0][0];
        case 2: return &g_Z[0][0][0][0];
        case 3: return &g_Z[1][0][0][0];
        case 4: return &g_T[0][0][0];
        case 5: return &g_M[0][0][0][0];
        default: return &g_M[1][0][0][0];
    }
}

// ================= mean =================
__global__ __launch_bounds__(256) void k_mean(const float* __restrict__ x) {
    __shared__ float sm[256];
    int c = blockIdx.x;
    const float4* row = (const float4*)(x + (size_t)c * NT);
    float s = 0.f;
    for (int i = threadIdx.x; i < NT / 4; i += 256) {
        float4 v = row[i];
        s += (v.x + v.y) + (v.z + v.w);
    }
    int t = threadIdx.x;
    sm[t] = s; __syncthreads();
    for (int o = 128; o > 0; o >>= 1) { if (t < o) sm[t] += sm[t + o]; __syncthreads(); }
    if (t == 0) g_mu[c] = sm[0] * (1.f / NT);
}

// ================= X -> bf16 hi/lo row-major AND transposed =================
__global__ __launch_bounds__(256) void k_cvt(const float* __restrict__ x) {
    __shared__ float ts[32][129];
    int g = blockIdx.z, k0 = blockIdx.y * 32, n0 = blockIdx.x * 128;
    int t = threadIdx.x;
    #pragma unroll
    for (int q = 0; q < 16; q++) {
        int idx = t + 256 * q;
        int r = idx >> 7, c = idx & 127;
        size_t o = (size_t)(g * LL + k0 + r) * NT + n0 + c;
        float v = x[o];
        ts[r][c] = v;
        __nv_bfloat16 h = __float2bfloat16(v);
        __nv_bfloat16 l = __float2bfloat16(v - __bfloat162float(h));
        gX_hi[o] = h;
        gX_lo[o] = l;
    }
    __syncthreads();
    #pragma unroll
    for (int q = 0; q < 2; q++) {
        int task = t + 256 * q;
        int n = task >> 2, oct = task & 3;
        union { ush s[8]; uint4 v; } ph, pl;
        #pragma unroll
        for (int e = 0; e < 8; e++) {
            float vv = ts[oct * 8 + e][n];
            __nv_bfloat16 h = __float2bfloat16(vv);
            float hf = __bfloat162float(h);
            __nv_bfloat16 l = __float2bfloat16(vv - hf);
            ph.s[e] = *(ush*)&h;
            pl.s[e] = *(ush*)&l;
        }
        size_t dst = (size_t)(g * NT + n0 + n) * LL + k0 + oct * 8;
        *(uint4*)&gXT_hi[dst] = ph.v;
        *(uint4*)&gXT_lo[dst] = pl.v;
    }
}

#define SRS 40   // smem row stride in bf16 elems (32 data + 8 pad)

// ================= cov partials via mma.sync bf16 split =================
__global__ __launch_bounds__(256) void k_cov_mma() {
    __shared__ __align__(16) ush sAh[128 * SRS];
    __shared__ __align__(16) ush sAl[128 * SRS];
    __shared__ __align__(16) ush sBh[128 * SRS];
    __shared__ __align__(16) ush sBl[128 * SRS];
    const int TIa[10] = {0,1,1,2,2,2,3,3,3,3};
    const int TJa[10] = {0,0,1,0,1,2,0,1,2,3};
    int t = threadIdx.x, lane = t & 31, wid = t >> 5;
    int wm = wid >> 2, wn = wid & 3;
    int ti = TIa[blockIdx.x] * 128, tj = TJa[blockIdx.x] * 128;
    int g = blockIdx.y, sp = blockIdx.z;

    const __nv_bfloat16* Ah = gX_hi + (size_t)(g * LL + ti) * NT + sp * KCH;
    const __nv_bfloat16* Al = gX_lo + (size_t)(g * LL + ti) * NT + sp * KCH;
    const __nv_bfloat16* Bh = gX_hi + (size_t)(g * LL + tj) * NT + sp * KCH;
    const __nv_bfloat16* Bl = gX_lo + (size_t)(g * LL + tj) * NT + sp * KCH;

    float acc[4][4][4];
    #pragma unroll
    for (int mi = 0; mi < 4; mi++)
        #pragma unroll
        for (int ni = 0; ni < 4; ni++)
            #pragma unroll
            for (int e = 0; e < 4; e++) acc[mi][ni][e] = 0.f;

    int aph = lane >> 3;
    int arow = (aph & 1) * 8 + (lane & 7);
    int acol = (aph >> 1) * 8;
    int brow = lane & 7;
    int bcol = ((lane >> 3) & 1) * 8;

    u32 bAh = smem_u32(sAh), bAl = smem_u32(sAl);
    u32 bBh = smem_u32(sBh), bBl = smem_u32(sBl);

    int ldr = t >> 2, ldc = (t & 3) * 8;

    for (int ck = 0; ck < KCH / 32; ck++) {
        int k0 = ck * 32;
        __syncthreads();
        #pragma unroll
        for (int q = 0; q < 2; q++) {
            int r = ldr + q * 64;
            u32 so = r * SRS + ldc;
            *(uint4*)&sAh[so] = *(const uint4*)(Ah + (size_t)r * NT + k0 + ldc);
            *(uint4*)&sAl[so] = *(const uint4*)(Al + (size_t)r * NT + k0 + ldc);
            *(uint4*)&sBh[so] = *(const uint4*)(Bh + (size_t)r * NT + k0 + ldc);
            *(uint4*)&sBl[so] = *(const uint4*)(Bl + (size_t)r * NT + k0 + ldc);
        }
        __syncthreads();
        #pragma unroll
        for (int kk = 0; kk < 32; kk += 16) {
            u32 Ahf[4][4], Alf[4][4];
            #pragma unroll
            for (int mi = 0; mi < 4; mi++) {
                u32 off = ((wm * 64 + mi * 16 + arow) * SRS + kk + acol) * 2;
                ldsm_x4(Ahf[mi][0], Ahf[mi][1], Ahf[mi][2], Ahf[mi][3], bAh + off);
                ldsm_x4(Alf[mi][0], Alf[mi][1], Alf[mi][2], Alf[mi][3], bAl + off);
            }
            #pragma unroll
            for (int ni = 0; ni < 4; ni++) {
                u32 off = ((wn * 32 + ni * 8 + brow) * SRS + kk + bcol) * 2;
                u32 bh0, bh1, bl0, bl1;
                ldsm_x2(bh0, bh1, bBh + off);
                ldsm_x2(bl0, bl1, bBl + off);
                #pragma unroll
                for (int mi = 0; mi < 4; mi++) {
                    mma_bf16(acc[mi][ni], Ahf[mi][0], Ahf[mi][1], Ahf[mi][2], Ahf[mi][3], bh0, bh1);
                    mma_bf16(acc[mi][ni], Ahf[mi][0], Ahf[mi][1], Ahf[mi][2], Ahf[mi][3], bl0, bl1);
                    mma_bf16(acc[mi][ni], Alf[mi][0], Alf[mi][1], Alf[mi][2], Alf[mi][3], bh0, bh1);
                }
            }
        }
    }

    float* base = &g_part[sp][g][0][0];
    #pragma unroll
    for (int mi = 0; mi < 4; mi++) {
        int r0 = ti + wm * 64 + mi * 16 + (lane >> 2);
        #pragma unroll
        for (int ni = 0; ni < 4; ni++) {
            int col = tj + wn * 32 + ni * 8 + 2 * (lane & 3);
            *(float2*)(base + (size_t)r0 * LL + col) =
                make_float2(acc[mi][ni][0], acc[mi][ni][1]);
            *(float2*)(base + (size_t)(r0 + 8) * LL + col) =
                make_float2(acc[mi][ni][2], acc[mi][ni][3]);
        }
    }
}

// ================= reduce partials -> A =================
__global__ __launch_bounds__(256) void k_cov_reduce() {
    int g = blockIdx.y;
    int idx = blockIdx.x * 256 + threadIdx.x;
    int i = idx >> 9, j = idx & 511;
    if (i < j) return;
    float s = 0.f;
    #pragma unroll
    for (int sp = 0; sp < KS; sp++) s += g_part[sp][g][i][j];
    float v = s * (1.f / NT) - g_mu[g * LL + i] * g_mu[g * LL + j];
    if (i == j) v += EPSV;
    g_A[g][i][j] = v;
    g_A[g][j][i] = v;
}

// ================= power iteration =================
__global__ void k_pi_init() {
    int idx = blockIdx.x * 256 + threadIdx.x;
    if (idx < GG * LL) {
        unsigned h = (unsigned)idx * 1103515245u + 12345u;
        ((float*)g_pv)[idx] = 0.5f + (float)(h & 1023u) * (1.0f / 1024.0f);
    }
}

__global__ __launch_bounds__(256) void k_matvec(int inb) {
    int g = blockIdx.y;
    __shared__ float vs[LL];
    for (int i = threadIdx.x; i < LL; i += 256) vs[i] = g_pv[inb][g][i];
    __syncthreads();
    int warp = threadIdx.x >> 5, lane = threadIdx.x & 31;
    int row0 = blockIdx.x * 32 + warp * 4;
    for (int r = 0; r < 4; r++) {
        int i = row0 + r;
        const float* Ar = &g_A[g][i][0];
        float s = 0.f;
        for (int k = lane; k < LL; k += 32) s += Ar[k] * vs[k];
        #pragma unroll
        for (int o = 16; o > 0; o >>= 1) s += __shfl_down_sync(0xffffffffu, s, o);
        if (lane == 0) g_pv[1 - inb][g][i] = s;
    }
}

__global__ void k_rq() {
    int g = blockIdx.x, i = threadIdx.x;
    __shared__ float r1[512], r2[512];
    float v = g_pv[0][g][i], u = g_pv[1][g][i];
    r1[i] = v * u; r2[i] = v * v; __syncthreads();
    for (int o = 256; o > 0; o >>= 1) {
        if (i < o) { r1[i] += r1[i + o]; r2[i] += r2[i + o]; }
        __syncthreads();
    }
    if (i == 0) g_scal[g] = r1[0] / r2[0];
}

// ================= NS init: Y0, T0 (bf16 hi/lo only) =================
__global__ __launch_bounds__(256) void k_ns_init() {
    int g = blockIdx.y;
    int idx = blockIdx.x * 256 + threadIdx.x;
    int i = idx >> 9, j = idx & 511;
    float invc = 1.0f / (1.05f * g_scal[g]);
    float y = g_A[g][i][j] * invc;
    float t0 = (i == j ? 1.5f : 0.0f) - 0.5f * y;
    __nv_bfloat16 yh = __float2bfloat16(y);
    g_bh[0][g][i][j] = yh;
    g_bl[0][g][i][j] = __float2bfloat16(y - __bfloat162float(yh));
    __nv_bfloat16 th = __float2bfloat16(t0);
    g_bh[2][g][i][j] = th;
    g_bl[2][g][i][j] = __float2bfloat16(t0 - __bfloat162float(th));
}

// ================= M0 = sigma I - A (bf16) + fnorm partials =================
__global__ __launch_bounds__(256) void k_shift() {
    int g = blockIdx.y;
    int base = blockIdx.x * 16384;
    float sigma = 1.15f * g_scal[g];
    float ss = 0.f;
    for (int q = 0; q < 64; q++) {
        int idx = base + threadIdx.x + 256 * q;
        int i = idx >> 9, j = idx & 511;
        float v = (i == j ? sigma : 0.0f) - g_A[g][i][j];
        __nv_bfloat16 h = __float2bfloat16(v);
        g_bh[5][g][i][j] = h;
        g_bl[5][g][i][j] = __float2bfloat16(v - __bfloat162float(h));
        ss += v * v;
    }
    __shared__ float rsm[256];
    int t = threadIdx.x;
    rsm[t] = ss; __syncthreads();
    for (int o = 128; o > 0; o >>= 1) { if (t < o) rsm[t] += rsm[t + o]; __syncthreads(); }
    if (t == 0) g_red2[0][g][blockIdx.x] = rsm[0];
}

// ================= chain GEMM via mma.sync bf16 split, up to 3 ops per launch =================
// All chain matrices are symmetric (polynomials in A) -> B fragment fed from rows.
// mode 0: C = 1.5 I - 0.5 (A B) ; mode 1: C = A B ;
// mode 2: C = (A B) * rsqrt(sum g_red2[rs]); block sumsq -> g_red2[ws]
// wf: also write fp32 C (only where an fp32 consumer exists)
__global__ __launch_bounds__(256) void k_chain3(ChainOp o0, ChainOp o1, ChainOp o2) {
    __shared__ __align__(16) ush sAh[128 * SRS];
    __shared__ __align__(16) ush sAl[128 * SRS];
    __shared__ __align__(16) ush sBh[128 * SRS];
    __shared__ __align__(16) ush sBl[128 * SRS];
    int opi = blockIdx.z >> 2;
    int g = blockIdx.z & 3;
    ChainOp op = (opi == 0) ? o0 : (opi == 1 ? o1 : o2);
    int t = threadIdx.x, lane = t & 31, wid = t >> 5;
    int wm = wid >> 2, wn = wid & 3;
    int i0 = blockIdx.y * 128, j0 = blockIdx.x * 128;

    const __nv_bfloat16* Ah = &g_bh[op.ida][g][i0][0];
    const __nv_bfloat16* Al = &g_bl[op.ida][g][i0][0];
    const __nv_bfloat16* Bh = &g_bh[op.idb][g][j0][0];
    const __nv_bfloat16* Bl = &g_bl[op.idb][g][j0][0];

    float scale = 1.0f;
    if (op.mode == 2) {
        float fs = 0.f;
        #pragma unroll
        for (int q = 0; q < 16; q++) fs += g_red2[op.rs][g][q];
        scale = rsqrtf(fs);
    }

    float acc[4][4][4];
    #pragma unroll
    for (int mi = 0; mi < 4; mi++)
        #pragma unroll
        for (int ni = 0; ni < 4; ni++)
            #pragma unroll
            for (int e = 0; e < 4; e++) acc[mi][ni][e] = 0.f;

    int aph = lane >> 3;
    int arow = (aph & 1) * 8 + (lane & 7);
    int acol = (aph >> 1) * 8;
    int brow = lane & 7;
    int bcol = ((lane >> 3) & 1) * 8;

    u32 bAh = smem_u32(sAh), bAl = smem_u32(sAl);
    u32 bBh = smem_u32(sBh), bBl = smem_u32(sBl);

    int ldr = t >> 2, ldc = (t & 3) * 8;

    for (int ck = 0; ck < 16; ck++) {
        int k0 = ck * 32;
        __syncthreads();
        #pragma unroll
        for (int q = 0; q < 2; q++) {
            int r = ldr + q * 64;
            u32 so = r * SRS + ldc;
            *(uint4*)&sAh[so] = *(const uint4*)(Ah + (size_t)r * LL + k0 + ldc);
            *(uint4*)&sAl[so] = *(const uint4*)(Al + (size_t)r * LL + k0 + ldc);
            *(uint4*)&sBh[so] = *(const uint4*)(Bh + (size_t)r * LL + k0 + ldc);
            *(uint4*)&sBl[so] = *(const uint4*)(Bl + (size_t)r * LL + k0 + ldc);
        }
        __syncthreads();
        #pragma unroll
        for (int kk = 0; kk < 32; kk += 16) {
            u32 Ahf[4][4], Alf[4][4];
            #pragma unroll
            for (int mi = 0; mi < 4; mi++) {
                u32 off = ((wm * 64 + mi * 16 + arow) * SRS + kk + acol) * 2;
                ldsm_x4(Ahf[mi][0], Ahf[mi][1], Ahf[mi][2], Ahf[mi][3], bAh + off);
                ldsm_x4(Alf[mi][0], Alf[mi][1], Alf[mi][2], Alf[mi][3], bAl + off);
            }
            #pragma unroll
            for (int ni = 0; ni < 4; ni++) {
                u32 off = ((wn * 32 + ni * 8 + brow) * SRS + kk + bcol) * 2;
                u32 bh0, bh1, bl0, bl1;
                ldsm_x2(bh0, bh1, bBh + off);
                ldsm_x2(bl0, bl1, bBl + off);
                #pragma unroll
                for (int mi = 0; mi < 4; mi++) {
                    mma_bf16(acc[mi][ni], Ahf[mi][0], Ahf[mi][1], Ahf[mi][2], Ahf[mi][3], bh0, bh1);
                    mma_bf16(acc[mi][ni], Ahf[mi][0], Ahf[mi][1], Ahf[mi][2], Ahf[mi][3], bl0, bl1);
                    mma_bf16(acc[mi][ni], Alf[mi][0], Alf[mi][1], Alf[mi][2], Alf[mi][3], bh0, bh1);
                }
            }
        }
    }

    float* Cf = bufptr(op.idc) + (size_t)g * LL * LL;
    __nv_bfloat16* Ch = &g_bh[op.idc][g][0][0];
    __nv_bfloat16* Cl = &g_bl[op.idc][g][0][0];
    float ss = 0.f;
    #pragma unroll
    for (int mi = 0; mi < 4; mi++) {
        int r0 = i0 + wm * 64 + mi * 16 + (lane >> 2);
        int r1 = r0 + 8;
        #pragma unroll
        for (int ni = 0; ni < 4; ni++) {
            int col = j0 + wn * 32 + ni * 8 + 2 * (lane & 3);
            float v00 = acc[mi][ni][0], v01 = acc[mi][ni][1];
            float v10 = acc[mi][ni][2], v11 = acc[mi][ni][3];
            if (op.mode == 0) {
                v00 = (r0 == col     ? 1.5f : 0.0f) - 0.5f * v00;
                v01 = (r0 == col + 1 ? 1.5f : 0.0f) - 0.5f * v01;
                v10 = (r1 == col     ? 1.5f : 0.0f) - 0.5f * v10;
                v11 = (r1 == col + 1 ? 1.5f : 0.0f) - 0.5f * v11;
            } else if (op.mode == 2) {
                v00 *= scale; v01 *= scale; v10 *= scale; v11 *= scale;
                ss += v00 * v00 + v01 * v01 + v10 * v10 + v11 * v11;
            }
            if (op.wf) {
                *(float2*)(Cf + (size_t)r0 * LL + col) = make_float2(v00, v01);
                *(float2*)(Cf + (size_t)r1 * LL + col) = make_float2(v10, v11);
            }
            __nv_bfloat16 h00 = __float2bfloat16(v00), h01 = __float2bfloat16(v01);
            __nv_bfloat16 h10 = __float2bfloat16(v10), h11 = __float2bfloat16(v11);
            u32 hp0 = ((u32)(*(ush*)&h01) << 16) | (u32)(*(ush*)&h00);
            u32 hp1 = ((u32)(*(ush*)&h11) << 16) | (u32)(*(ush*)&h10);
            *(u32*)(Ch + (size_t)r0 * LL + col) = hp0;
            *(u32*)(Ch + (size_t)r1 * LL + col) = hp1;
            __nv_bfloat16 l00 = __float2bfloat16(v00 - __bfloat162float(h00));
            __nv_bfloat16 l01 = __float2bfloat16(v01 - __bfloat162float(h01));
            __nv_bfloat16 l10 = __float2bfloat16(v10 - __bfloat162float(h10));
            __nv_bfloat16 l11 = __float2bfloat16(v11 - __bfloat162float(h11));
            u32 lp0 = ((u32)(*(ush*)&l01) << 16) | (u32)(*(ush*)&l00);
            u32 lp1 = ((u32)(*(ush*)&l11) << 16) | (u32)(*(ush*)&l10);
            *(u32*)(Cl + (size_t)r0 * LL + col) = lp0;
            *(u32*)(Cl + (size_t)r1 * LL + col) = lp1;
        }
    }
    if (op.mode == 2) {
        __shared__ float rsm[256];
        rsm[t] = ss; __syncthreads();
        for (int o = 128; o > 0; o >>= 1) { if (t < o) rsm[t] += rsm[t + o]; __syncthreads(); }
        if (t == 0) g_red2[op.ws][g][blockIdx.y * 4 + blockIdx.x] = rsm[0];
    }
}

// ================= eigenvector extraction =================
__global__ void k_colnorm() {
    int g = blockIdx.x, j = threadIdx.x;
    const float* M = &g_M[0][g][0][0];
    float s = 0.f;
    for (int i = 0; i < LL; i++) { float m = M[(size_t)i * LL + j]; s += m * m; }
    __shared__ float sv[512]; __shared__ int si[512];
    sv[j] = s; si[j] = j; __syncthreads();
    for (int o = 256; o > 0; o >>= 1) {
        if (j < o) { if (sv[j + o] > sv[j]) { sv[j] = sv[j + o]; si[j] = si[j + o]; } }
        __syncthreads();
    }
    int jm = si[0];
    float inv = rsqrtf(sv[0]);
    g_v[g][j] = M[(size_t)j * LL + jm] * inv;
}

__global__ void k_rayleigh() {
    int g = blockIdx.x, i = threadIdx.x;
    __shared__ float vs[512];
    vs[i] = g_v[g][i]; __syncthreads();
    float u = 0.f;
    const float* Ac = &g_A[g][0][0];
    for (int k = 0; k < 512; k++) u = fmaf(Ac[(size_t)k * 512 + i], vs[k], u);
    __shared__ float r1[512], r2[512];
    r1[i] = u * vs[i]; r2[i] = vs[i] * vs[i]; __syncthreads();
    for (int o = 256; o > 0; o >>= 1) {
        if (i < o) { r1[i] += r1[i + o]; r2[i] += r2[i + o]; }
        __syncthreads();
    }
    if (i == 0) g_scal[8 + g] = r1[0] / r2[0];
}

// ================= P = Z/sqrt(c) - lam^{-1/2} v v^T (+ bf16 split) =================
__global__ __launch_bounds__(256) void k_subspace(int zid) {
    int g = blockIdx.y;
    int idx = blockIdx.x * 256 + threadIdx.x;
    int i = idx >> 9, j = idx & 511;
    const float* Z = bufptr(zid) + (size_t)g * LL * LL;
    float c = 1.05f * g_scal[g];
    float lam = g_scal[8 + g];
    float p = Z[(size_t)i * 512 + j] * rsqrtf(c) - rsqrtf(lam) * g_v[g][i] * g_v[g][j];
    g_P[g][i][j] = p;
    __nv_bfloat16 h = __float2bfloat16(p);
    gP_hi[g][i][j] = h;
    gP_lo[g][i][j] = __float2bfloat16(p - __bfloat162float(h));
}

// ================= beta = bias - w * (P mu) =================
__global__ void k_beta(const float* __restrict__ w, const float* __restrict__ b) {
    int g = blockIdx.x, i = threadIdx.x;
    __shared__ float mus[512];
    mus[i] = g_mu[g * LL + i]; __syncthreads();
    float s = 0.f;
    const float* Pc = &g_P[g][0][0];
    for (int k = 0; k < 512; k++) s = fmaf(Pc[(size_t)k * 512 + i], mus[k], s);
    int c = g * LL + i;
    g_beta[c] = b[c] - w[c] * s;
}

// ================= apply via mma.sync bf16 split (round-11 proven) =================
__global__ __launch_bounds__(256) void k_apply_mma(const float* __restrict__ w,
                                                   float* __restrict__ out) {
    __shared__ __align__(16) ush sAh[128 * SRS];
    __shared__ __align__(16) ush sAl[128 * SRS];
    __shared__ __align__(16) ush sBh[128 * SRS];
    __shared__ __align__(16) ush sBl[128 * SRS];
    int t = threadIdx.x, lane = t & 31, wid = t >> 5;
    int wm = wid >> 2, wn = wid & 3;
    int n0 = blockIdx.x * 128, i0 = blockIdx.y * 128, g = blockIdx.z;

    const __nv_bfloat16* Ph = &gP_hi[g][0][0];
    const __nv_bfloat16* Pl = &gP_lo[g][0][0];
    const __nv_bfloat16* Xh = gXT_hi + (size_t)g * NT * LL;
    const __nv_bfloat16* Xl = gXT_lo + (size_t)g * NT * LL;

    float acc[4][4][4];
    #pragma unroll
    for (int mi = 0; mi < 4; mi++)
        #pragma unroll
        for (int ni = 0; ni < 4; ni++)
            #pragma unroll
            for (int e = 0; e < 4; e++) acc[mi][ni][e] = 0.f;

    int aph = lane >> 3;
    int arow = (aph & 1) * 8 + (lane & 7);
    int acol = (aph >> 1) * 8;
    int brow = lane & 7;
    int bcol = ((lane >> 3) & 1) * 8;

    u32 bAh = smem_u32(sAh), bAl = smem_u32(sAl);
    u32 bBh = smem_u32(sBh), bBl = smem_u32(sBl);

    int ldr = t >> 2, ldc = (t & 3) * 8;

    for (int ck = 0; ck < 16; ck++) {
        int k0 = ck * 32;
        __syncthreads();
        #pragma unroll
        for (int q = 0; q < 2; q++) {
            int r = ldr + q * 64;
            u32 so = r * SRS + ldc;
            *(uint4*)&sAh[so] = *(const uint4*)(Ph + (size_t)(i0 + r) * LL + k0 + ldc);
            *(uint4*)&sAl[so] = *(const uint4*)(Pl + (size_t)(i0 + r) * LL + k0 + ldc);
            *(uint4*)&sBh[so] = *(const uint4*)(Xh + (size_t)(n0 + r) * LL + k0 + ldc);
            *(uint4*)&sBl[so] = *(const uint4*)(Xl + (size_t)(n0 + r) * LL + k0 + ldc);
        }
        __syncthreads();
        #pragma unroll
        for (int kk = 0; kk < 32; kk += 16) {
            u32 Ahf[4][4], Alf[4][4];
            #pragma unroll
            for (int mi = 0; mi < 4; mi++) {
                u32 off = ((wm * 64 + mi * 16 + arow) * SRS + kk + acol) * 2;
                ldsm_x4(Ahf[mi][0], Ahf[mi][1], Ahf[mi][2], Ahf[mi][3], bAh + off);
                ldsm_x4(Alf[mi][0], Alf[mi][1], Alf[mi][2], Alf[mi][3], bAl + off);
            }
            #pragma unroll
            for (int ni = 0; ni < 4; ni++) {
                u32 off = ((wn * 32 + ni * 8 + brow) * SRS + kk + bcol) * 2;
                u32 bh0, bh1, bl0, bl1;
                ldsm_x2(bh0, bh1, bBh + off);
                ldsm_x2(bl0, bl1, bBl + off);
                #pragma unroll
                for (int mi = 0; mi < 4; mi++) {
                    mma_bf16(acc[mi][ni], Ahf[mi][0], Ahf[mi][1], Ahf[mi][2], Ahf[mi][3], bh0, bh1);
                    mma_bf16(acc[mi][ni], Ahf[mi][0], Ahf[mi][1], Ahf[mi][2], Ahf[mi][3], bl0, bl1);
                    mma_bf16(acc[mi][ni], Alf[mi][0], Alf[mi][1], Alf[mi][2], Alf[mi][3], bh0, bh1);
                }
            }
        }
    }

    #pragma unroll
    for (int mi = 0; mi < 4; mi++) {
        int r0 = i0 + wm * 64 + mi * 16 + (lane >> 2);
        int ch0 = g * LL + r0, ch1 = ch0 + 8;
        float w0 = w[ch0], be0 = g_beta[ch0];
        float w1 = w[ch1], be1 = g_beta[ch1];
        #pragma unroll
        for (int ni = 0; ni < 4; ni++) {
            int col = n0 + wn * 32 + ni * 8 + 2 * (lane & 3);
            float2 v0, v1;
            v0.x = fmaf(w0, acc[mi][ni][0], be0);
            v0.y = fmaf(w0, acc[mi][ni][1], be0);
            v1.x = fmaf(w1, acc[mi][ni][2], be1);
            v1.y = fmaf(w1, acc[mi][ni][3], be1);
            *(float2*)(out + (size_t)ch0 * NT + col) = v0;
            *(float2*)(out + (size_t)ch1 * NT + col) = v1;
        }
    }
}

// ================= launch =================
extern "C" void kernel_launch(void* const* d_in, const int* in_sizes, int n_in,
                              void* d_out, int out_size) {
    const float* x = (const float*)d_in[0];
    const float* w = (const float*)d_in[1];
    const float* b = (const float*)d_in[2];
    float* out = (float*)d_out;

    k_mean<<<CC, 256>>>(x);
    k_cvt<<<dim3(128, 16, GG), 256>>>(x);
    k_cov_mma<<<dim3(10, GG, KS), 256>>>();
    k_cov_reduce<<<dim3(1024, GG), 256>>>();

    k_pi_init<<<8, 256>>>();
    for (int m = 0; m < 7; m++)
        k_matvec<<<dim3(16, GG), 256>>>(m & 1);
    k_rq<<<GG, 512>>>();

    k_ns_init<<<dim3(1024, GG), 256>>>();
    k_shift<<<dim3(16, GG), 256>>>();

    // NS ops (buffers 0=Y0 1=Y1 2=Z0 3=Z1 4=T) — 7 serial levels
    ChainOp ns1  = {0, 2, 1, 1, 0, 0, 0};   // Y1 = Y0 T0
    ChainOp ns2  = {2, 1, 4, 0, 0, 0, 0};   // T1 = 1.5I - 0.5 Z1 Y1
    ChainOp ns3a = {1, 4, 0, 1, 0, 0, 0};   // Y2
    ChainOp ns3b = {4, 2, 3, 1, 0, 0, 0};   // Z2
    ChainOp ns4  = {3, 0, 4, 0, 0, 0, 0};   // T2
    ChainOp ns5a = {0, 4, 1, 1, 0, 0, 0};   // Y3
    ChainOp ns5b = {4, 3, 2, 1, 0, 0, 0};   // Z3
    ChainOp ns6  = {2, 1, 4, 0, 0, 0, 0};   // T3
    ChainOp ns7  = {4, 2, 3, 1, 0, 0, 1};   // Z4 -> buf 3 (fp32 for k_subspace)
    ChainOp sq[SQ_ITERS];
    for (int k = 0; k < SQ_ITERS; k++) {
        ChainOp o = {5 + (k & 1), 5 + (k & 1), 5 + 1 - (k & 1), 2,
                     k & 1, 1 - (k & 1), (k == SQ_ITERS - 1) ? 1 : 0};
        sq[k] = o;
    }
    ChainOp dummy = {4, 4, 4, 1, 0, 0, 0};

    // co-scheduled NS + SQ levels (independent chains)
    k_chain3<<<dim3(4, 4, 8),  256>>>(ns1,  sq[0], dummy);
    k_chain3<<<dim3(4, 4, 8),  256>>>(ns2,  sq[1], dummy);
    k_chain3<<<dim3(4, 4, 12), 256>>>(ns3a, ns3b,  sq[2]);
    k_chain3<<<dim3(4, 4, 8),  256>>>(ns4,  sq[3], dummy);
    k_chain3<<<dim3(4, 4, 12), 256>>>(ns5a, ns5b,  sq[4]);
    k_chain3<<<dim3(4, 4, 8),  256>>>(ns6,  sq[5], dummy);
    k_chain3<<<dim3(4, 4, 8),  256>>>(ns7,  sq[6], dummy);
    for (int k = 7; k < SQ_ITERS; k++)
        k_chain3<<<dim3(4, 4, 4), 256>>>(sq[k], dummy, dummy);

    // final squaring output: SQ_ITERS=10 -> last op reads buf 6, writes buf 5 (g_M[0]) ✓
    k_colnorm<<<GG, 512>>>();
    k_rayleigh<<<GG, 512>>>();
    k_subspace<<<dim3(1024, GG), 256>>>(3);
    k_beta<<<GG, 512>>>(w, b);
    k_apply_mma<<<dim3(128, 4, GG), 256>>>(w, out);
}